// round 3
// baseline (speedup 1.0000x reference)
#include <cuda_runtime.h>
#include <cstdint>

#define H 224
#define W 224
#define NPIX (H * W)          // 50176
#define NIMG 256
#define K2_THREADS 1024
#define HIST_WORDS 32768      // 65536 u16 bins packed in u32

// ---------------- scratch (no allocations allowed) ----------------
__device__ unsigned char g_buf[(size_t)NIMG * NPIX + 64];
__device__ unsigned int  d_sum[NIMG];
__device__ unsigned int  d_sumsq[NIMG];
__device__ float         d_feat[NIMG * 4 * 4];   // [n][offset][con,dis,hom,asm]

// ---------------- Kernel 1: quantize + moments ----------------
__global__ __launch_bounds__(256) void quantize_kernel(const float* __restrict__ x) {
    const int n = blockIdx.x;            // image index = b*16 + f
    const int b = n >> 4, f = n & 15;
    const size_t base = (size_t)(b * 48 + f) * NPIX;
    const float4* __restrict__ x0 = (const float4*)(x + base);
    const float4* __restrict__ x1 = (const float4*)(x + base + (size_t)16 * NPIX);
    const float4* __restrict__ x2 = (const float4*)(x + base + (size_t)32 * NPIX);
    unsigned int* __restrict__ gout = (unsigned int*)(g_buf + (size_t)n * NPIX);

    unsigned int s = 0, q = 0;
    for (int v = threadIdx.x; v < NPIX / 4; v += 256) {
        float4 p0 = x0[v], p1 = x1[v], p2 = x2[v];
        // match jnp.mean -> sum/3, then *255, floor (avoid FMA/reassociation)
        int g0 = (int)__fmul_rn(__fdiv_rn(__fadd_rn(__fadd_rn(p0.x, p1.x), p2.x), 3.0f), 255.0f);
        int g1 = (int)__fmul_rn(__fdiv_rn(__fadd_rn(__fadd_rn(p0.y, p1.y), p2.y), 3.0f), 255.0f);
        int g2 = (int)__fmul_rn(__fdiv_rn(__fadd_rn(__fadd_rn(p0.z, p1.z), p2.z), 3.0f), 255.0f);
        int g3 = (int)__fmul_rn(__fdiv_rn(__fadd_rn(__fadd_rn(p0.w, p1.w), p2.w), 3.0f), 255.0f);
        s += (unsigned)(g0 + g1 + g2 + g3);
        q += (unsigned)(g0 * g0 + g1 * g1 + g2 * g2 + g3 * g3);
        gout[v] = (unsigned)g0 | ((unsigned)g1 << 8) | ((unsigned)g2 << 16) | ((unsigned)g3 << 24);
    }
    // block reduction (exact, u32)
    s = __reduce_add_sync(0xFFFFFFFFu, s);
    q = __reduce_add_sync(0xFFFFFFFFu, q);
    __shared__ unsigned int ss[8], sq[8];
    const int warp = threadIdx.x >> 5, lane = threadIdx.x & 31;
    if (lane == 0) { ss[warp] = s; sq[warp] = q; }
    __syncthreads();
    if (threadIdx.x == 0) {
        unsigned int ts = 0, tq = 0;
        #pragma unroll
        for (int i = 0; i < 8; i++) { ts += ss[i]; tq += sq[i]; }
        d_sum[n] = ts; d_sumsq[n] = tq;
    }
}

// ---------------- Kernel 2: per-(image,offset) GLCM ----------------
template <int DR, int DC>
__device__ __forceinline__ void glcm_body(int n, int out_idx, unsigned int* hist) {
    constexpr int A0 = (DC < 0) ? 1 : 0;     // a-column shift
    constexpr int B0 = (DC > 0) ? 1 : 0;     // b-column shift
    constexpr int R  = H - DR;
    constexpr int C2 = W - ((DC < 0) ? -DC : DC);
    constexpr int CHUNKS = 14;               // 14*16 = 224 columns per row
    constexpr float NP = (float)(R * C2);

    const unsigned char* __restrict__ g = g_buf + (size_t)n * NPIX;
    const int tid = threadIdx.x;

    for (int i = tid; i < HIST_WORDS; i += K2_THREADS) hist[i] = 0u;
    __syncthreads();

    // ---- pair accumulation: 16 pairs per iteration, vectorized loads ----
    const int total = R * CHUNKS;
    for (int m = tid; m < total; m += K2_THREADS) {
        const int r = m / CHUNKS;
        const int k = m - r * CHUNKS;
        const unsigned int* rowa = (const unsigned int*)(g + r * W);
        const unsigned int* rowb = (const unsigned int*)(g + (r + DR) * W);
        uint4 av = ((const uint4*)rowa)[k];
        uint4 bv = ((const uint4*)rowb)[k];
        unsigned int A[5] = { av.x, av.y, av.z, av.w, 0u };
        unsigned int B[5] = { bv.x, bv.y, bv.z, bv.w, 0u };
        if (A0) A[4] = rowa[k * 4 + 4];      // padded buffer: safe at row/image end
        if (B0) B[4] = rowb[k * 4 + 4];
        unsigned int aw[4], bw[4];
        #pragma unroll
        for (int w = 0; w < 4; w++) {
            aw[w] = A0 ? __funnelshift_r(A[w], A[w + 1], 8) : A[w];
            bw[w] = B0 ? __funnelshift_r(B[w], B[w + 1], 8) : B[w];
        }
        const int cbase = k * 16;
        #pragma unroll
        for (int w = 0; w < 4; w++) {
            #pragma unroll
            for (int p = 0; p < 4; p++) {
                const int c = cbase + w * 4 + p;
                if (C2 == W || c < C2) {
                    unsigned int a = (aw[w] >> (p * 8)) & 255u;
                    unsigned int b = (bw[w] >> (p * 8)) & 255u;
                    // swizzled bin layout: slot(i,j) = i*256 + ((j + 2i) & 255)
                    unsigned int slot = (a << 8) | ((b + 2u * a) & 255u);
                    atomicAdd(&hist[slot >> 1], 1u << ((slot & 1u) << 4));
                }
            }
        }
    }
    __syncthreads();

    // ---- stats over 64K bins (swizzle makes transpose read conflict-free) ----
    float s2 = 0.f, scon = 0.f, sdis = 0.f, shom = 0.f;
    #pragma unroll 4
    for (int it = 0; it < 65536 / K2_THREADS; ++it) {
        const int l = tid + (it << 10);
        const int i = l >> 8, j = l & 255;
        const unsigned int slot1 = (unsigned)((i << 8) | ((j + 2 * i) & 255));
        const unsigned int w1 = hist[slot1 >> 1];
        const unsigned int c1 = (w1 >> ((slot1 & 1u) << 4)) & 0xFFFFu;
        const unsigned int slot2 = (unsigned)((j << 8) | ((i + 2 * j) & 255));
        const unsigned int w2 = hist[slot2 >> 1];
        const unsigned int c2 = (w2 >> ((slot2 & 1u) << 4)) & 0xFFFFu;
        const float cs = (float)(c1 + c2);
        s2 += cs * cs;
        const float d  = (float)(i - j);
        const float d2 = d * d;
        const float cf = (float)c1;
        scon += cf * d2;
        sdis += cf * fabsf(d);
        shom += cf / (1.0f + d2);
    }

    // deterministic block reduction
    __shared__ float red[4][32];
    float v0 = s2, v1 = scon, v2 = sdis, v3 = shom;
    #pragma unroll
    for (int off = 16; off; off >>= 1) {
        v0 += __shfl_xor_sync(0xFFFFFFFFu, v0, off);
        v1 += __shfl_xor_sync(0xFFFFFFFFu, v1, off);
        v2 += __shfl_xor_sync(0xFFFFFFFFu, v2, off);
        v3 += __shfl_xor_sync(0xFFFFFFFFu, v3, off);
    }
    const int warp = tid >> 5, lane = tid & 31;
    if (lane == 0) { red[0][warp] = v0; red[1][warp] = v1; red[2][warp] = v2; red[3][warp] = v3; }
    __syncthreads();
    if (tid < 32) {
        float a0 = red[0][tid], a1 = red[1][tid], a2 = red[2][tid], a3 = red[3][tid];
        #pragma unroll
        for (int off = 16; off; off >>= 1) {
            a0 += __shfl_xor_sync(0xFFFFFFFFu, a0, off);
            a1 += __shfl_xor_sync(0xFFFFFFFFu, a1, off);
            a2 += __shfl_xor_sync(0xFFFFFFFFu, a2, off);
            a3 += __shfl_xor_sync(0xFFFFFFFFu, a3, off);
        }
        if (tid == 0) {
            d_feat[out_idx * 4 + 0] = a1 / NP;                   // contrast
            d_feat[out_idx * 4 + 1] = a2 / NP;                   // dissimilarity
            d_feat[out_idx * 4 + 2] = a3 / NP;                   // homogeneity
            d_feat[out_idx * 4 + 3] = a0 / (4.0f * NP * NP);     // ASM
        }
    }
}

__global__ __launch_bounds__(K2_THREADS, 1) void glcm_kernel() {
    extern __shared__ unsigned int hist[];
    const int bx = blockIdx.x;
    const int n = bx >> 2;
    const int o = bx & 3;
    switch (o) {
        case 0: glcm_body<0, 1>(n, bx, hist); break;   // (0,1)
        case 1: glcm_body<1, 1>(n, bx, hist); break;   // (1,1)
        case 2: glcm_body<1, 0>(n, bx, hist); break;   // (1,0)
        default: glcm_body<1, -1>(n, bx, hist); break; // (1,-1)
    }
}

// ---------------- Kernel 3: finalize ----------------
__global__ __launch_bounds__(256) void finalize_kernel(float* __restrict__ out) {
    const int n = threadIdx.x;
    const double inv = 1.0 / (double)NPIX;
    const double mean = (double)d_sum[n] * inv;
    double var = (double)d_sumsq[n] * inv - mean * mean;
    if (var < 0.0) var = 0.0;
    float con = 0.f, dis = 0.f, hom = 0.f, as = 0.f;
    #pragma unroll
    for (int o = 0; o < 4; o++) {
        const float* f4 = &d_feat[(n * 4 + o) * 4];
        con += f4[0]; dis += f4[1]; hom += f4[2]; as += f4[3];
    }
    con *= 0.25f; dis *= 0.25f; hom *= 0.25f; as *= 0.25f;
    float* o6 = out + n * 6;
    o6[0] = (float)sqrt(var);
    o6[1] = con;
    o6[2] = dis;
    o6[3] = hom;
    o6[4] = as;
    o6[5] = sqrtf(as);
}

// ---------------- launch ----------------
extern "C" void kernel_launch(void* const* d_in, const int* in_sizes, int n_in,
                              void* d_out, int out_size) {
    (void)in_sizes; (void)n_in; (void)out_size;
    const float* x = (const float*)d_in[0];
    float* out = (float*)d_out;

    cudaFuncSetAttribute(glcm_kernel, cudaFuncAttributeMaxDynamicSharedMemorySize,
                         HIST_WORDS * sizeof(unsigned int));

    quantize_kernel<<<NIMG, 256>>>(x);
    glcm_kernel<<<NIMG * 4, K2_THREADS, HIST_WORDS * sizeof(unsigned int)>>>();
    finalize_kernel<<<1, 256>>>(out);
}

// round 5
// speedup vs baseline: 1.0801x; 1.0801x over previous
#include <cuda_runtime.h>
#include <cstdint>

#define H 224
#define W 224
#define NPIX (H * W)          // 50176
#define NIMG 256
#define K2_THREADS 1024
#define HIST_WORDS 16384      // 65536 u8 bins packed 4-per-u32 = 64 KB

// ---------------- scratch (no allocations allowed) ----------------
__device__ unsigned char g_buf[(size_t)NIMG * NPIX + 64];
__device__ unsigned int  d_sum4[NIMG * 4];
__device__ unsigned int  d_sumsq4[NIMG * 4];
__device__ float         d_feat[NIMG * 4 * 4];   // [n][offset][con,dis,hom,asm]

// ---------------- Kernel 1: quantize + moments (4 CTAs per image) ----------------
__global__ __launch_bounds__(256) void quantize_kernel(const float* __restrict__ x) {
    const int n = blockIdx.x >> 2;       // image index = b*16 + f
    const int q = blockIdx.x & 3;        // quarter
    const int b = n >> 4, f = n & 15;
    const size_t base = (size_t)(b * 48 + f) * NPIX;
    const float4* __restrict__ x0 = (const float4*)(x + base);
    const float4* __restrict__ x1 = (const float4*)(x + base + (size_t)16 * NPIX);
    const float4* __restrict__ x2 = (const float4*)(x + base + (size_t)32 * NPIX);
    unsigned int* __restrict__ gout = (unsigned int*)(g_buf + (size_t)n * NPIX);

    const int v0 = q * (NPIX / 16);      // NPIX/4 float4 words total, quarter = 3136
    const int v1 = v0 + (NPIX / 16);

    unsigned int s = 0, qq = 0;
    for (int v = v0 + threadIdx.x; v < v1; v += 256) {
        float4 p0 = x0[v], p1 = x1[v], p2 = x2[v];
        // match jnp.mean -> sum/3, then *255, floor (no FMA/reassociation)
        int g0 = (int)__fmul_rn(__fdiv_rn(__fadd_rn(__fadd_rn(p0.x, p1.x), p2.x), 3.0f), 255.0f);
        int g1 = (int)__fmul_rn(__fdiv_rn(__fadd_rn(__fadd_rn(p0.y, p1.y), p2.y), 3.0f), 255.0f);
        int g2 = (int)__fmul_rn(__fdiv_rn(__fadd_rn(__fadd_rn(p0.z, p1.z), p2.z), 3.0f), 255.0f);
        int g3 = (int)__fmul_rn(__fdiv_rn(__fadd_rn(__fadd_rn(p0.w, p1.w), p2.w), 3.0f), 255.0f);
        s  += (unsigned)(g0 + g1 + g2 + g3);
        qq += (unsigned)(g0 * g0 + g1 * g1 + g2 * g2 + g3 * g3);
        gout[v] = (unsigned)g0 | ((unsigned)g1 << 8) | ((unsigned)g2 << 16) | ((unsigned)g3 << 24);
    }
    // block reduction (exact, u32)
    s  = __reduce_add_sync(0xFFFFFFFFu, s);
    qq = __reduce_add_sync(0xFFFFFFFFu, qq);
    __shared__ unsigned int ss[8], sq[8];
    const int warp = threadIdx.x >> 5, lane = threadIdx.x & 31;
    if (lane == 0) { ss[warp] = s; sq[warp] = qq; }
    __syncthreads();
    if (threadIdx.x == 0) {
        unsigned int ts = 0, tq = 0;
        #pragma unroll
        for (int i = 0; i < 8; i++) { ts += ss[i]; tq += sq[i]; }
        d_sum4[blockIdx.x] = ts; d_sumsq4[blockIdx.x] = tq;
    }
}

// ---------------- Kernel 2: per-(image,offset) GLCM, u8 smem histogram ----------------
template <int DR, int DC>
__device__ __forceinline__ void glcm_body(int n, int out_idx, unsigned int* hist) {
    constexpr int A0 = (DC < 0) ? 1 : 0;     // a-column shift
    constexpr int B0 = (DC > 0) ? 1 : 0;     // b-column shift
    constexpr int R  = H - DR;
    constexpr int C2 = W - ((DC < 0) ? -DC : DC);
    constexpr int CHUNKS = 14;               // 14*16 = 224 columns per row
    constexpr float NP = (float)(R * C2);

    const unsigned char* __restrict__ g = g_buf + (size_t)n * NPIX;
    const int tid = threadIdx.x;

    // zero 64 KB histogram (uint4 stores)
    {
        uint4 z = make_uint4(0u, 0u, 0u, 0u);
        uint4* h4 = (uint4*)hist;
        #pragma unroll
        for (int i = tid; i < HIST_WORDS / 4; i += K2_THREADS) h4[i] = z;
    }
    __syncthreads();

    // ---- pair accumulation: 16 pairs per iteration, vectorized loads ----
    const int total = R * CHUNKS;
    for (int m = tid; m < total; m += K2_THREADS) {
        const int r = m / CHUNKS;
        const int k = m - r * CHUNKS;
        const unsigned int* rowa = (const unsigned int*)(g + r * W);
        const unsigned int* rowb = (const unsigned int*)(g + (r + DR) * W);
        uint4 av = ((const uint4*)rowa)[k];
        uint4 bv = ((const uint4*)rowb)[k];
        unsigned int A[5] = { av.x, av.y, av.z, av.w, 0u };
        unsigned int B[5] = { bv.x, bv.y, bv.z, bv.w, 0u };
        if (A0) A[4] = rowa[k * 4 + 4];      // padded buffer: safe at row/image end
        if (B0) B[4] = rowb[k * 4 + 4];
        unsigned int aw[4], bw[4];
        #pragma unroll
        for (int w = 0; w < 4; w++) {
            aw[w] = A0 ? __funnelshift_r(A[w], A[w + 1], 8) : A[w];
            bw[w] = B0 ? __funnelshift_r(B[w], B[w + 1], 8) : B[w];
        }
        const int cbase = k * 16;
        #pragma unroll
        for (int w = 0; w < 4; w++) {
            #pragma unroll
            for (int p = 0; p < 4; p++) {
                const int c = cbase + w * 4 + p;
                if (C2 == W || c < C2) {
                    unsigned int a = (aw[w] >> (p * 8)) & 255u;
                    unsigned int b = (bw[w] >> (p * 8)) & 255u;
                    // swizzled u8 bin layout: slot(i,j) = i*256 + ((j + 4i) & 255)
                    unsigned int slot = (a << 8) | ((b + 4u * a) & 255u);
                    atomicAdd(&hist[slot >> 2], 1u << ((slot & 3u) << 3));
                }
            }
        }
    }
    __syncthreads();

    // ---- stats over 64K bins (swizzle makes transpose read conflict-free) ----
    float s2 = 0.f, scon = 0.f, sdis = 0.f, shom = 0.f;
    #pragma unroll 4
    for (int it = 0; it < 65536 / K2_THREADS; ++it) {
        const int l = tid + (it << 10);
        const int i = l >> 8, j = l & 255;
        const unsigned int slot1 = (unsigned)((i << 8) | ((j + 4 * i) & 255));
        const unsigned int c1 = (hist[slot1 >> 2] >> ((slot1 & 3u) << 3)) & 255u;
        const unsigned int slot2 = (unsigned)((j << 8) | ((i + 4 * j) & 255));
        const unsigned int c2 = (hist[slot2 >> 2] >> ((slot2 & 3u) << 3)) & 255u;
        const float cs = (float)(c1 + c2);
        s2 += cs * cs;
        const float d  = (float)(i - j);
        const float d2 = d * d;
        const float cf = (float)c1;
        scon += cf * d2;
        sdis += cf * fabsf(d);
        shom += cf / (1.0f + d2);
    }

    // deterministic block reduction
    __shared__ float red[4][32];
    float v0 = s2, v1 = scon, v2 = sdis, v3 = shom;
    #pragma unroll
    for (int off = 16; off; off >>= 1) {
        v0 += __shfl_xor_sync(0xFFFFFFFFu, v0, off);
        v1 += __shfl_xor_sync(0xFFFFFFFFu, v1, off);
        v2 += __shfl_xor_sync(0xFFFFFFFFu, v2, off);
        v3 += __shfl_xor_sync(0xFFFFFFFFu, v3, off);
    }
    const int warp = tid >> 5, lane = tid & 31;
    if (lane == 0) { red[0][warp] = v0; red[1][warp] = v1; red[2][warp] = v2; red[3][warp] = v3; }
    __syncthreads();
    if (tid < 32) {
        float a0 = red[0][tid], a1 = red[1][tid], a2 = red[2][tid], a3 = red[3][tid];
        #pragma unroll
        for (int off = 16; off; off >>= 1) {
            a0 += __shfl_xor_sync(0xFFFFFFFFu, a0, off);
            a1 += __shfl_xor_sync(0xFFFFFFFFu, a1, off);
            a2 += __shfl_xor_sync(0xFFFFFFFFu, a2, off);
            a3 += __shfl_xor_sync(0xFFFFFFFFu, a3, off);
        }
        if (tid == 0) {
            d_feat[out_idx * 4 + 0] = a1 / NP;                   // contrast
            d_feat[out_idx * 4 + 1] = a2 / NP;                   // dissimilarity
            d_feat[out_idx * 4 + 2] = a3 / NP;                   // homogeneity
            d_feat[out_idx * 4 + 3] = a0 / (4.0f * NP * NP);     // ASM
        }
    }
}

__global__ __launch_bounds__(K2_THREADS, 2) void glcm_kernel() {
    extern __shared__ unsigned int hist[];
    const int bx = blockIdx.x;
    const int n = bx >> 2;
    const int o = bx & 3;
    switch (o) {
        case 0: glcm_body<0, 1>(n, bx, hist); break;   // (0,1)
        case 1: glcm_body<1, 1>(n, bx, hist); break;   // (1,1)
        case 2: glcm_body<1, 0>(n, bx, hist); break;   // (1,0)
        default: glcm_body<1, -1>(n, bx, hist); break; // (1,-1)
    }
}

// ---------------- Kernel 3: finalize ----------------
__global__ __launch_bounds__(256) void finalize_kernel(float* __restrict__ out) {
    const int n = threadIdx.x;
    unsigned int tsum = 0, tsq = 0;
    #pragma unroll
    for (int q = 0; q < 4; q++) { tsum += d_sum4[n * 4 + q]; tsq += d_sumsq4[n * 4 + q]; }
    const double inv = 1.0 / (double)NPIX;
    const double mean = (double)tsum * inv;
    double var = (double)tsq * inv - mean * mean;
    if (var < 0.0) var = 0.0;
    float con = 0.f, dis = 0.f, hom = 0.f, as = 0.f;
    #pragma unroll
    for (int o = 0; o < 4; o++) {
        const float* f4 = &d_feat[(n * 4 + o) * 4];
        con += f4[0]; dis += f4[1]; hom += f4[2]; as += f4[3];
    }
    con *= 0.25f; dis *= 0.25f; hom *= 0.25f; as *= 0.25f;
    float* o6 = out + n * 6;
    o6[0] = (float)sqrt(var);
    o6[1] = con;
    o6[2] = dis;
    o6[3] = hom;
    o6[4] = as;
    o6[5] = sqrtf(as);
}

// ---------------- launch ----------------
extern "C" void kernel_launch(void* const* d_in, const int* in_sizes, int n_in,
                              void* d_out, int out_size) {
    (void)in_sizes; (void)n_in; (void)out_size;
    const float* x = (const float*)d_in[0];
    float* out = (float*)d_out;

    cudaFuncSetAttribute(glcm_kernel, cudaFuncAttributeMaxDynamicSharedMemorySize,
                         HIST_WORDS * sizeof(unsigned int));

    quantize_kernel<<<NIMG * 4, 256>>>(x);
    glcm_kernel<<<NIMG * 4, K2_THREADS, HIST_WORDS * sizeof(unsigned int)>>>();
    finalize_kernel<<<1, 256>>>(out);
}